// round 2
// baseline (speedup 1.0000x reference)
#include <cuda_runtime.h>
#include <cuda_bf16.h>
#include <math.h>

// ---------------- problem constants ----------------
#define SQ   2048
#define BB   2
#define DIM  1024
#define NH   16
#define HD   64
#define NTOK 4096          // SQ*BB
#define NE   8
#define DFF  4096
#define CAP  2048
#define LN_EPS 1e-5f

// ---------------- scratch (device globals; no allocs allowed) ----------------
__device__ float g_qkv [NTOK * 3 * DIM];       // SA qkv
__device__ float g_attn[NTOK * DIM];           // attention output (reused SA/CA)
__device__ float g_x1  [NTOK * DIM];           // after SA o-proj
__device__ float g_qca [NTOK * DIM];           // CA q
__device__ float g_kvca[NTOK * 2 * DIM];       // CA k,v from memory
__device__ float g_x2  [NTOK * DIM];           // after CA o-proj (MoE input)
__device__ float g_probs[NTOK * NE];
__device__ float g_gatev[NTOK * 2];
__device__ int   g_gidx [NTOK * 2];
__device__ int   g_sl   [NTOK * 2];            // slot per (token,choice); -1 = dropped
__device__ int   g_rows [NE];                  // occupied rows per expert
__device__ float g_aux;
__device__ float g_buf[NE * CAP * DIM];        // dispatched tokens
__device__ float g_h  [(size_t)NE * CAP * DFF];// hidden
__device__ float g_y  [NE * CAP * DIM];        // expert outputs
__device__ float g_x3 [NTOK * DIM];            // combined MoE output

// ---------------- helpers ----------------
__device__ __forceinline__ float gelu_exact(float x) {
    return 0.5f * x * (1.0f + erff(x * 0.70710678118654752440f));
}

// ---------------- generic tiled SGEMM ----------------
// C[n,m] = sum_k A[n,k] * (TRANSB ? B[m,k] : B[k,m]) + bias[m]  (optional GELU)
// 128x128x8 tiles, 256 threads, 8x8 microtiles. Dims assumed multiples of 128/8.
template<int TRANSB, int DOGELU>
__global__ void __launch_bounds__(256, 2) gemm_kernel(
    const float* __restrict__ A, const float* __restrict__ B,
    const float* __restrict__ bias, float* __restrict__ C,
    int Mcols, int K, int lda, int ldb, int ldc,
    long long sA, long long sB, long long sBias, long long sC,
    const int* __restrict__ rows_used)
{
    const int z = blockIdx.z;
    if (rows_used) { if ((int)(blockIdx.y * 128) >= rows_used[z]) return; }
    A += (long long)z * sA;  B += (long long)z * sB;  C += (long long)z * sC;
    bias += (long long)z * sBias;

    __shared__ float As[8][132];
    __shared__ float Bs[8][132];

    const int tid = threadIdx.x;
    const int tx  = tid & 15, ty = tid >> 4;
    const int rowBase = blockIdx.y * 128;
    const int colBase = blockIdx.x * 128;

    const int arow = tid >> 1;
    const int ak   = (tid & 1) * 4;
    const int bk_nn = tid >> 5;
    const int bn_nn = (tid & 31) * 4;

    float acc[8][8];
    #pragma unroll
    for (int i = 0; i < 8; i++)
        #pragma unroll
        for (int j = 0; j < 8; j++) acc[i][j] = 0.f;

    const float* Aptr = A + (long long)(rowBase + arow) * lda + ak;
    const float* Bptr;
    if (TRANSB) Bptr = B + (long long)(colBase + arow) * ldb + ak;
    else        Bptr = B + (long long)bk_nn * ldb + colBase + bn_nn;

    for (int k0 = 0; k0 < K; k0 += 8) {
        float4 av = *(const float4*)(Aptr + k0);
        As[ak+0][arow] = av.x; As[ak+1][arow] = av.y;
        As[ak+2][arow] = av.z; As[ak+3][arow] = av.w;
        if (TRANSB) {
            float4 bv = *(const float4*)(Bptr + k0);
            Bs[ak+0][arow] = bv.x; Bs[ak+1][arow] = bv.y;
            Bs[ak+2][arow] = bv.z; Bs[ak+3][arow] = bv.w;
        } else {
            float4 bv = *(const float4*)(Bptr + (long long)k0 * ldb);
            *(float4*)&Bs[bk_nn][bn_nn] = bv;
        }
        __syncthreads();

        #pragma unroll
        for (int kk = 0; kk < 8; kk++) {
            float4 a0 = *(const float4*)&As[kk][ty * 8];
            float4 a1 = *(const float4*)&As[kk][ty * 8 + 4];
            float4 b0 = *(const float4*)&Bs[kk][tx * 8];
            float4 b1 = *(const float4*)&Bs[kk][tx * 8 + 4];
            float a[8] = {a0.x,a0.y,a0.z,a0.w,a1.x,a1.y,a1.z,a1.w};
            float b[8] = {b0.x,b0.y,b0.z,b0.w,b1.x,b1.y,b1.z,b1.w};
            #pragma unroll
            for (int i = 0; i < 8; i++)
                #pragma unroll
                for (int j = 0; j < 8; j++)
                    acc[i][j] = fmaf(a[i], b[j], acc[i][j]);
        }
        __syncthreads();
    }

    #pragma unroll
    for (int i = 0; i < 8; i++) {
        const int r = rowBase + ty * 8 + i;
        float* cp = C + (long long)r * ldc + colBase + tx * 8;
        #pragma unroll
        for (int jj = 0; jj < 8; jj += 4) {
            float4 v;
            v.x = acc[i][jj+0] + bias[colBase + tx*8 + jj + 0];
            v.y = acc[i][jj+1] + bias[colBase + tx*8 + jj + 1];
            v.z = acc[i][jj+2] + bias[colBase + tx*8 + jj + 2];
            v.w = acc[i][jj+3] + bias[colBase + tx*8 + jj + 3];
            if (DOGELU) {
                v.x = gelu_exact(v.x); v.y = gelu_exact(v.y);
                v.z = gelu_exact(v.z); v.w = gelu_exact(v.w);
            }
            *(float4*)(cp + jj) = v;
        }
    }
}

// ---------------- flash attention (fp32, Br=Bc=64, hd=64) ----------------
// token layout: row(s,b) = s*BB + b; head columns at h*HD within ld.
#define ATTN_SMEM (4 * 64 * 65 * 4)
__global__ void __launch_bounds__(256) attn_kernel(
    const float* __restrict__ Qb, int ldq,
    const float* __restrict__ Kb, int ldk,
    const float* __restrict__ Vb, int ldv,
    float* __restrict__ Ob, int ldo, int Skv)
{
    extern __shared__ float sm[];
    float* Qs = sm;
    float* Ks = sm + 64 * 65;
    float* Vs = sm + 2 * 64 * 65;
    float* Ss = sm + 3 * 64 * 65;

    const int b = blockIdx.z, h = blockIdx.y, qt = blockIdx.x;
    const int tid = threadIdx.x, tx = tid & 15, ty = tid >> 4;
    const float* Q = Qb + h * HD;
    const float* Kp = Kb + h * HD;
    const float* Vp = Vb + h * HD;

    for (int u = tid; u < 64 * 16; u += 256) {
        int r = u >> 4, c4 = (u & 15) << 2;
        long long tok = (long long)(qt * 64 + r) * BB + b;
        float4 v = *(const float4*)(Q + tok * ldq + c4);
        float* d = Qs + r * 65 + c4;
        d[0] = v.x * 0.125f; d[1] = v.y * 0.125f;
        d[2] = v.z * 0.125f; d[3] = v.w * 0.125f;
    }

    float o[4][4];
    float mrow[4], lrow[4];
    #pragma unroll
    for (int i = 0; i < 4; i++) {
        mrow[i] = -1e30f; lrow[i] = 0.f;
        #pragma unroll
        for (int j = 0; j < 4; j++) o[i][j] = 0.f;
    }

    const int nkt = Skv / 64;
    for (int kt = 0; kt < nkt; kt++) {
        __syncthreads();
        for (int u = tid; u < 64 * 16; u += 256) {
            int r = u >> 4, c4 = (u & 15) << 2;
            long long tok = (long long)(kt * 64 + r) * BB + b;
            float4 kv = *(const float4*)(Kp + tok * ldk + c4);
            float* kd = Ks + r * 65 + c4;
            kd[0] = kv.x; kd[1] = kv.y; kd[2] = kv.z; kd[3] = kv.w;
            float4 vv = *(const float4*)(Vp + tok * ldv + c4);
            float* vd = Vs + r * 65 + c4;
            vd[0] = vv.x; vd[1] = vv.y; vd[2] = vv.z; vd[3] = vv.w;
        }
        __syncthreads();

        float s[4][4];
        #pragma unroll
        for (int i = 0; i < 4; i++)
            #pragma unroll
            for (int j = 0; j < 4; j++) s[i][j] = 0.f;

        #pragma unroll 4
        for (int k = 0; k < 64; k++) {
            float a[4], bb2[4];
            #pragma unroll
            for (int i = 0; i < 4; i++) a[i] = Qs[(ty * 4 + i) * 65 + k];
            #pragma unroll
            for (int j = 0; j < 4; j++) bb2[j] = Ks[(tx * 4 + j) * 65 + k];
            #pragma unroll
            for (int i = 0; i < 4; i++)
                #pragma unroll
                for (int j = 0; j < 4; j++)
                    s[i][j] = fmaf(a[i], bb2[j], s[i][j]);
        }

        #pragma unroll
        for (int i = 0; i < 4; i++) {
            float rmax = fmaxf(fmaxf(s[i][0], s[i][1]), fmaxf(s[i][2], s[i][3]));
            #pragma unroll
            for (int off = 8; off >= 1; off >>= 1)
                rmax = fmaxf(rmax, __shfl_xor_sync(0xffffffffu, rmax, off));
            float mn = fmaxf(mrow[i], rmax);
            float sc = __expf(mrow[i] - mn);
            float p0 = __expf(s[i][0] - mn);
            float p1 = __expf(s[i][1] - mn);
            float p2 = __expf(s[i][2] - mn);
            float p3 = __expf(s[i][3] - mn);
            float* sp = Ss + (ty * 4 + i) * 65 + tx * 4;
            sp[0] = p0; sp[1] = p1; sp[2] = p2; sp[3] = p3;
            float ps = p0 + p1 + p2 + p3;
            #pragma unroll
            for (int off = 8; off >= 1; off >>= 1)
                ps += __shfl_xor_sync(0xffffffffu, ps, off);
            lrow[i] = lrow[i] * sc + ps;
            mrow[i] = mn;
            #pragma unroll
            for (int j = 0; j < 4; j++) o[i][j] *= sc;
        }
        __syncthreads();

        #pragma unroll 4
        for (int k = 0; k < 64; k++) {
            float ss[4], vv[4];
            #pragma unroll
            for (int i = 0; i < 4; i++) ss[i] = Ss[(ty * 4 + i) * 65 + k];
            #pragma unroll
            for (int j = 0; j < 4; j++) vv[j] = Vs[k * 65 + tx * 4 + j];
            #pragma unroll
            for (int i = 0; i < 4; i++)
                #pragma unroll
                for (int j = 0; j < 4; j++)
                    o[i][j] = fmaf(ss[i], vv[j], o[i][j]);
        }
    }

    #pragma unroll
    for (int i = 0; i < 4; i++) {
        float inv = 1.0f / lrow[i];
        long long tok = (long long)(qt * 64 + ty * 4 + i) * BB + b;
        float* op = Ob + tok * ldo + h * HD + tx * 4;
        op[0] = o[i][0] * inv; op[1] = o[i][1] * inv;
        op[2] = o[i][2] * inv; op[3] = o[i][3] * inv;
    }
}

// ---------------- gating: softmax(x @ w_gate) + top-2 ----------------
__global__ void __launch_bounds__(128) gate_kernel(
    const float* __restrict__ x, const float* __restrict__ wg,
    float* __restrict__ probs, float* __restrict__ gatev, int* __restrict__ gidx)
{
    const int t = blockIdx.x;
    const int tid = threadIdx.x;
    __shared__ float red[128][8];
    float acc[8];
    #pragma unroll
    for (int e = 0; e < 8; e++) acc[e] = 0.f;
    for (int d = tid; d < DIM; d += 128) {
        float xv = x[(long long)t * DIM + d];
        const float4* w = (const float4*)(wg + d * 8);
        float4 w0 = w[0], w1 = w[1];
        acc[0] += xv * w0.x; acc[1] += xv * w0.y; acc[2] += xv * w0.z; acc[3] += xv * w0.w;
        acc[4] += xv * w1.x; acc[5] += xv * w1.y; acc[6] += xv * w1.z; acc[7] += xv * w1.w;
    }
    #pragma unroll
    for (int e = 0; e < 8; e++) red[tid][e] = acc[e];
    __syncthreads();
    for (int s = 64; s > 0; s >>= 1) {
        if (tid < s)
            #pragma unroll
            for (int e = 0; e < 8; e++) red[tid][e] += red[tid + s][e];
        __syncthreads();
    }
    if (tid == 0) {
        float l[8], mx = -1e30f;
        #pragma unroll
        for (int e = 0; e < 8; e++) { l[e] = red[0][e]; mx = fmaxf(mx, l[e]); }
        float sum = 0.f;
        #pragma unroll
        for (int e = 0; e < 8; e++) { l[e] = __expf(l[e] - mx); sum += l[e]; }
        float inv = 1.0f / sum;
        #pragma unroll
        for (int e = 0; e < 8; e++) { l[e] *= inv; probs[t * 8 + e] = l[e]; }
        int i1 = 0; float v1 = l[0];
        #pragma unroll
        for (int e = 1; e < 8; e++) if (l[e] > v1) { v1 = l[e]; i1 = e; }
        int i2 = -1; float v2 = -1.f;
        #pragma unroll
        for (int e = 0; e < 8; e++) if (e != i1 && l[e] > v2) { v2 = l[e]; i2 = e; }
        gatev[2 * t] = v1; gatev[2 * t + 1] = v2;
        gidx[2 * t] = i1;  gidx[2 * t + 1] = i2;
    }
}

// ---------------- routing: sequential per-expert position scan + aux ----------------
__global__ void __launch_bounds__(256) route_kernel(
    const int* __restrict__ gidx, const float* __restrict__ probs,
    int* __restrict__ sl, int* __restrict__ rows, float* __restrict__ auxp)
{
    __shared__ signed char s1[NTOK];
    __shared__ signed char s2[NTOK];
    __shared__ int cnt1[8];
    __shared__ float pr[256 * 8];
    const int tid = threadIdx.x;

    for (int i = tid; i < NTOK; i += 256) {
        int2 v = ((const int2*)gidx)[i];
        s1[i] = (signed char)v.x; s2[i] = (signed char)v.y;
    }
    float lp[8];
    #pragma unroll
    for (int e = 0; e < 8; e++) lp[e] = 0.f;
    for (int i = tid; i < NTOK; i += 256) {
        const float4* p = (const float4*)(probs + i * 8);
        float4 p0 = p[0], p1 = p[1];
        lp[0] += p0.x; lp[1] += p0.y; lp[2] += p0.z; lp[3] += p0.w;
        lp[4] += p1.x; lp[5] += p1.y; lp[6] += p1.z; lp[7] += p1.w;
    }
    #pragma unroll
    for (int e = 0; e < 8; e++) pr[tid * 8 + e] = lp[e];
    __syncthreads();
    for (int s = 128; s > 0; s >>= 1) {
        if (tid < s)
            #pragma unroll
            for (int e = 0; e < 8; e++) pr[tid * 8 + e] += pr[(tid + s) * 8 + e];
        __syncthreads();
    }

    if (tid < 8) {                       // first-choice positions
        int e = tid, c = 0;
        #pragma unroll 1
        for (int i = 0; i < NTOK; i++)
            if (s1[i] == e) { sl[2 * i] = (c < CAP) ? c : -1; c++; }
        cnt1[e] = c;
    }
    __syncthreads();
    if (tid < 8) {                       // second-choice positions (offset by cnt1 total)
        int e = tid, base = cnt1[e], c = 0;
        #pragma unroll 1
        for (int i = 0; i < NTOK; i++)
            if (s2[i] == e) { int loc = base + c; sl[2 * i + 1] = (loc < CAP) ? loc : -1; c++; }
        int ru = cnt1[e] + c; if (ru > CAP) ru = CAP;
        rows[e] = ru;
    }
    __syncthreads();
    if (tid == 0) {
        float a = 0.f;
        for (int e = 0; e < 8; e++)
            a += ((float)cnt1[e] / (float)NTOK) * (pr[e] / (float)NTOK);
        *auxp = 0.01f * 8.0f * a;
    }
}

// ---------------- scatter tokens into expert buffer ----------------
__global__ void __launch_bounds__(256) scatter_kernel(
    const float* __restrict__ x, const int* __restrict__ gidx,
    const int* __restrict__ sl, float* __restrict__ buf)
{
    const int t = blockIdx.x, ch = blockIdx.y;
    const int s = sl[2 * t + ch];
    if (s < 0) return;
    const int e = gidx[2 * t + ch];
    const float4* src = (const float4*)(x + (long long)t * DIM);
    float4* dst = (float4*)(buf + ((size_t)e * CAP + s) * DIM);
    dst[threadIdx.x] = src[threadIdx.x];
}

// ---------------- gather expert outputs back ----------------
__global__ void __launch_bounds__(256) gather_kernel(
    const float* __restrict__ y, const int* __restrict__ gidx,
    const int* __restrict__ sl, const float* __restrict__ gatev,
    float* __restrict__ out)
{
    const int t = blockIdx.x;
    const float gv1 = gatev[2 * t], gv2 = gatev[2 * t + 1];
    const int s1 = sl[2 * t], s2 = sl[2 * t + 1];
    const int e1 = gidx[2 * t], e2 = gidx[2 * t + 1];
    float4 r = make_float4(0.f, 0.f, 0.f, 0.f);
    if (s1 >= 0) {
        float4 a = ((const float4*)(y + ((size_t)e1 * CAP + s1) * DIM))[threadIdx.x];
        r.x += gv1 * a.x; r.y += gv1 * a.y; r.z += gv1 * a.z; r.w += gv1 * a.w;
    }
    if (s2 >= 0) {
        float4 a = ((const float4*)(y + ((size_t)e2 * CAP + s2) * DIM))[threadIdx.x];
        r.x += gv2 * a.x; r.y += gv2 * a.y; r.z += gv2 * a.z; r.w += gv2 * a.w;
    }
    ((float4*)(out + (long long)t * DIM))[threadIdx.x] = r;
}

// ---------------- triple layernorm + output + aux ----------------
__device__ __forceinline__ float block_sum(float v, float* red) {
    int tid = threadIdx.x;
    red[tid] = v; __syncthreads();
    for (int s = 128; s > 0; s >>= 1) {
        if (tid < s) red[tid] += red[tid + s];
        __syncthreads();
    }
    float r = red[0]; __syncthreads();
    return r;
}

__global__ void __launch_bounds__(256) ln3_kernel(
    const float* __restrict__ x,
    const float* __restrict__ g1, const float* __restrict__ b1,
    const float* __restrict__ g2, const float* __restrict__ b2,
    const float* __restrict__ g3, const float* __restrict__ b3,
    float* __restrict__ out, const float* __restrict__ auxp, long long out_size)
{
    __shared__ float red[256];
    const int t = blockIdx.x, tid = threadIdx.x;
    float4 v = ((const float4*)(x + (long long)t * DIM))[tid];

    const float* gs[3] = {g1, g2, g3};
    const float* bs[3] = {b1, b2, b3};
    #pragma unroll
    for (int r3 = 0; r3 < 3; r3++) {
        float s = v.x + v.y + v.z + v.w;
        float mean = block_sum(s, red) * (1.0f / DIM);
        float dx = v.x - mean, dy = v.y - mean, dz = v.z - mean, dw = v.w - mean;
        float s2 = dx * dx + dy * dy + dz * dz + dw * dw;
        float var = block_sum(s2, red) * (1.0f / DIM);
        float rstd = rsqrtf(var + LN_EPS);
        float4 gg = ((const float4*)gs[r3])[tid];
        float4 bb = ((const float4*)bs[r3])[tid];
        v.x = dx * rstd * gg.x + bb.x;
        v.y = dy * rstd * gg.y + bb.y;
        v.z = dz * rstd * gg.z + bb.z;
        v.w = dw * rstd * gg.w + bb.w;
    }
    ((float4*)(out + (long long)t * DIM))[tid] = v;
    if (t == 0 && tid == 0 && out_size > (long long)NTOK * DIM)
        out[(long long)NTOK * DIM] = *auxp;
}

// ---------------- launch ----------------
extern "C" void kernel_launch(void* const* d_in, const int* in_sizes, int n_in,
                              void* d_out, int out_size) {
    const float* tgt      = (const float*)d_in[0];
    const float* mem      = (const float*)d_in[1];
    const float* w_qkv_sa = (const float*)d_in[2];
    const float* b_qkv_sa = (const float*)d_in[3];
    const float* w_o_sa   = (const float*)d_in[4];
    const float* b_o_sa   = (const float*)d_in[5];
    const float* w_qkv_ca = (const float*)d_in[6];
    const float* b_qkv_ca = (const float*)d_in[7];
    const float* w_o_ca   = (const float*)d_in[8];
    const float* b_o_ca   = (const float*)d_in[9];
    const float* ln1_g = (const float*)d_in[10];
    const float* ln1_b = (const float*)d_in[11];
    const float* ln2_g = (const float*)d_in[12];
    const float* ln2_b = (const float*)d_in[13];
    const float* ln3_g = (const float*)d_in[14];
    const float* ln3_b = (const float*)d_in[15];
    const float* w_gate = (const float*)d_in[16];
    const float* w1  = (const float*)d_in[17];
    const float* b1e = (const float*)d_in[18];
    const float* w2  = (const float*)d_in[19];
    const float* b2e = (const float*)d_in[20];
    float* out = (float*)d_out;

    float *qkv, *attn, *x1, *qca, *kvca, *x2, *probs, *gatev, *x3, *buf, *hbuf, *ybuf, *auxp;
    int *gidx, *sl, *rows;
    cudaGetSymbolAddress((void**)&qkv,  g_qkv);
    cudaGetSymbolAddress((void**)&attn, g_attn);
    cudaGetSymbolAddress((void**)&x1,   g_x1);
    cudaGetSymbolAddress((void**)&qca,  g_qca);
    cudaGetSymbolAddress((void**)&kvca, g_kvca);
    cudaGetSymbolAddress((void**)&x2,   g_x2);
    cudaGetSymbolAddress((void**)&probs,g_probs);
    cudaGetSymbolAddress((void**)&gatev,g_gatev);
    cudaGetSymbolAddress((void**)&gidx, g_gidx);
    cudaGetSymbolAddress((void**)&sl,   g_sl);
    cudaGetSymbolAddress((void**)&rows, g_rows);
    cudaGetSymbolAddress((void**)&auxp, g_aux);
    cudaGetSymbolAddress((void**)&buf,  g_buf);
    cudaGetSymbolAddress((void**)&hbuf, g_h);
    cudaGetSymbolAddress((void**)&ybuf, g_y);
    cudaGetSymbolAddress((void**)&x3,   g_x3);

    cudaFuncSetAttribute(attn_kernel, cudaFuncAttributeMaxDynamicSharedMemorySize, ATTN_SMEM);

    // 1) SA qkv projection: (4096x1024) @ (3072x1024)^T
    gemm_kernel<1,0><<<dim3(3072/128, NTOK/128, 1), 256>>>(
        tgt, w_qkv_sa, b_qkv_sa, qkv, 3072, DIM, DIM, DIM, 3072, 0, 0, 0, 0, nullptr);

    // 2) self-attention
    attn_kernel<<<dim3(SQ/64, NH, BB), 256, ATTN_SMEM>>>(
        qkv, 3 * DIM, qkv + DIM, 3 * DIM, qkv + 2 * DIM, 3 * DIM, attn, DIM, SQ);

    // 3) SA output projection
    gemm_kernel<1,0><<<dim3(DIM/128, NTOK/128, 1), 256>>>(
        attn, w_o_sa, b_o_sa, x1, DIM, DIM, DIM, DIM, DIM, 0, 0, 0, 0, nullptr);

    // 4) CA q projection from x1
    gemm_kernel<1,0><<<dim3(DIM/128, NTOK/128, 1), 256>>>(
        x1, w_qkv_ca, b_qkv_ca, qca, DIM, DIM, DIM, DIM, DIM, 0, 0, 0, 0, nullptr);

    // 5) CA k,v projection from memory
    gemm_kernel<1,0><<<dim3(2*DIM/128, NTOK/128, 1), 256>>>(
        mem, w_qkv_ca + (size_t)DIM * DIM, b_qkv_ca + DIM, kvca,
        2 * DIM, DIM, DIM, DIM, 2 * DIM, 0, 0, 0, 0, nullptr);

    // 6) cross-attention
    attn_kernel<<<dim3(SQ/64, NH, BB), 256, ATTN_SMEM>>>(
        qca, DIM, kvca, 2 * DIM, kvca + DIM, 2 * DIM, attn, DIM, SQ);

    // 7) CA output projection -> x2 (MoE input)
    gemm_kernel<1,0><<<dim3(DIM/128, NTOK/128, 1), 256>>>(
        attn, w_o_ca, b_o_ca, x2, DIM, DIM, DIM, DIM, DIM, 0, 0, 0, 0, nullptr);

    // 8) gating
    gate_kernel<<<NTOK, 128>>>(x2, w_gate, probs, gatev, gidx);

    // 9) routing (sequential position scan) + aux
    route_kernel<<<1, 256>>>(gidx, probs, sl, rows, auxp);

    // 10) scatter
    scatter_kernel<<<dim3(NTOK, 2), 256>>>(x2, gidx, sl, buf);

    // 11) expert FFN layer 1 (+GELU), batched over experts, row-skip
    gemm_kernel<0,1><<<dim3(DFF/128, CAP/128, NE), 256>>>(
        buf, w1, b1e, hbuf, DFF, DIM, DIM, DFF, DFF,
        (long long)CAP * DIM, (long long)DIM * DFF, DFF, (long long)CAP * DFF, rows);

    // 12) expert FFN layer 2, batched, row-skip
    gemm_kernel<0,0><<<dim3(DIM/128, CAP/128, NE), 256>>>(
        hbuf, w2, b2e, ybuf, DIM, DFF, DFF, DIM, DIM,
        (long long)CAP * DFF, (long long)DFF * DIM, DIM, (long long)CAP * DIM, rows);

    // 13) gather with gate weights
    gather_kernel<<<NTOK, 256>>>(ybuf, gidx, sl, gatev, x3);

    // 14) triple layernorm -> out, plus aux scalar
    ln3_kernel<<<NTOK, 256>>>(x3, ln1_g, ln1_b, ln2_g, ln2_b, ln3_g, ln3_b,
                              out, auxp, (long long)out_size);
}